// round 16
// baseline (speedup 1.0000x reference)
#include <cuda_runtime.h>
#include <cstdint>

#define BB     2048
#define INF    512
#define OUTF   512
#define NEXP   64
#define T      256
#define NQ     128           // out cols per CTA
#define MCH    64            // m rows per chunk (4 x m16 max)
#define KT     32            // fp32 k per tile -> 2 k16 mma steps
#define NTILES (INF / KT)    // 16

#define SWZ(o)  ((o) ^ (((o) >> 3) & 0x70))
#define OWF(s) ((uint32_t)(s) * 16384u)             // fp32 W stage: 128 rows x 128B
#define OXF(s) (32768u + (uint32_t)(s) * 8192u)     // fp32 X stage: 64 rows x 128B
#define OWB(s) (49152u + (uint32_t)(s) * 16384u)    // bf16 W: 128 rows x (64B hi | 64B lo)
#define OXB(s) (81920u + (uint32_t)(s) * 8192u)     // bf16 X: 64 rows x (hi|lo)
#define DYN_BYTES (98304 + 1024)

static __device__ __forceinline__ void cp16(uint32_t dst, const void* src) {
    asm volatile("cp.async.ca.shared.global [%0], [%1], 16;" :: "r"(dst), "l"(src));
}
static __device__ __forceinline__ void sts64(uint32_t a, uint32_t v0, uint32_t v1) {
    asm volatile("st.shared.v2.b32 [%0], {%1,%2};" :: "r"(a), "r"(v0), "r"(v1));
}
static __device__ __forceinline__ void lds128(uint32_t a, uint32_t& x, uint32_t& y,
                                              uint32_t& z, uint32_t& w) {
    asm volatile("ld.shared.v4.b32 {%0,%1,%2,%3}, [%4];"
                 : "=r"(x), "=r"(y), "=r"(z), "=r"(w) : "r"(a));
}
// split fp32 pair -> bf16x2 hi (truncate) + bf16x2 lo (rn of residual); elem0 = first
static __device__ __forceinline__ void cvt_pair(float vx, float vy,
                                                uint32_t &hi2, uint32_t &lo2) {
    uint32_t a = __float_as_uint(vx), b = __float_as_uint(vy);
    hi2 = __byte_perm(a, b, 0x7632);
    float la = vx - __uint_as_float(a & 0xFFFF0000u);
    float lb = vy - __uint_as_float(b & 0xFFFF0000u);
    asm("cvt.rn.bf16x2.f32 %0, %1, %2;" : "=r"(lo2) : "f"(lb), "f"(la));
}
#define LDSM4(r0,r1,r2,r3,a) asm volatile( \
    "ldmatrix.sync.aligned.m8n8.x4.shared.b16 {%0,%1,%2,%3}, [%4];" \
    : "=r"(r0),"=r"(r1),"=r"(r2),"=r"(r3) : "r"(a))
#define LDSM2(r0,r1,a) asm volatile( \
    "ldmatrix.sync.aligned.m8n8.x2.shared.b16 {%0,%1}, [%2];" \
    : "=r"(r0),"=r"(r1) : "r"(a))
#define MMA(c,a,b) asm volatile( \
    "mma.sync.aligned.m16n8k16.row.col.f32.bf16.bf16.f32 " \
    "{%0,%1,%2,%3}, {%4,%5,%6,%7}, {%8,%9}, {%0,%1,%2,%3};" \
    : "+f"((c)[0]),"+f"((c)[1]),"+f"((c)[2]),"+f"((c)[3]) \
    : "r"((a)[0]),"r"((a)[1]),"r"((a)[2]),"r"((a)[3]),"r"((b)[0]),"r"((b)[1]))

extern __shared__ char dynsmem[];

__global__ __launch_bounds__(T, 2)
void catlin_mma(const float* __restrict__ x, const unsigned* __restrict__ idw,
                const float* __restrict__ weight, float* __restrict__ out)
{
    __shared__ uint16_t slist[BB];
    __shared__ int scount;
    __shared__ unsigned sor;

    const int expert = blockIdx.x >> 2;
    const int nq     = blockIdx.x & 3;
    const int tid    = threadIdx.x;
    const int wid    = tid >> 5, lane = tid & 31;

    if (tid == 0) { scount = 0; sor = 0; }
    __syncthreads();

    unsigned myor = 0;
    for (int i = tid; i < BB / 2; i += T) myor |= idw[2 * i + 1];
    if (myor) atomicOr(&sor, myor);
    __syncthreads();
    const bool is64 = (sor == 0);

    for (int i = tid; i < BB; i += T) {
        int id = is64 ? (int)idw[2 * i] : (int)idw[i];
        if (id == expert) { int p = atomicAdd(&scount, 1); slist[p] = (uint16_t)i; }
    }
    __syncthreads();
    const int m = scount;
    if (m == 0) return;

    uint32_t sb = (uint32_t)__cvta_generic_to_shared(dynsmem);
    sb = (sb + 1023u) & ~1023u;

    const float* wexp = weight + ((size_t)(expert * OUTF + nq * NQ)) * INF;
    const int wq  = wid & 3;         // n subtile: 32 cols
    const int wm  = wid >> 2;        // m group 0/1
    const int n0w = wq * 32;
    const int r8  = lane & 7;
    const int g4  = lane >> 3;
    const int c4  = tid & 7;         // float4 column within 128B row
    const int rb  = tid >> 3;        // row base 0..31 (rows: i*32+rb)

    for (int mbase = 0; mbase < m; mbase += MCH) {
        const int rem = m - mbase;
        int nmt_tot = (rem + 15) >> 4; if (nmt_tot > 4) nmt_tot = 4;
        const int mh   = (nmt_tot + 1) >> 1;
        const int mt0  = wm ? mh : 0;
        const int nmyt = wm ? (nmt_tot - mh) : mh;

        // per-thread gathered X row pointers for this chunk (identity mapping)
        const float* xp[2];
        #pragma unroll
        for (int i = 0; i < 2; ++i) {
            int gr = mbase + i * 32 + rb; if (gr >= m) gr = m - 1;
            xp[i] = x + (size_t)slist[gr] * INF + c4 * 4;
        }

        float c[2][4][4];
        #pragma unroll
        for (int j = 0; j < 2; j++)
            #pragma unroll
            for (int b = 0; b < 4; b++)
                #pragma unroll
                for (int q = 0; q < 4; q++) c[j][b][q] = 0.f;

        auto cpis = [&](int t) {
            const int s = t & 1, kb = t * KT;
            #pragma unroll
            for (int i = 0; i < 4; ++i)
                cp16(sb + OWF(s) + SWZ((uint32_t)((i * 32 + rb) * 128 + c4 * 16)),
                     wexp + (size_t)(i * 32 + rb) * INF + kb + c4 * 4);
            #pragma unroll
            for (int i = 0; i < 2; ++i)
                cp16(sb + OXF(s) + SWZ((uint32_t)((i * 32 + rb) * 128 + c4 * 16)),
                     xp[i] + kb);
            asm volatile("cp.async.commit_group;" ::);
        };
        auto conv = [&](int t) {
            const int s = t & 1;
            #pragma unroll
            for (int i = 0; i < 4; ++i) {
                const uint32_t ro = (uint32_t)((i * 32 + rb) * 128);
                uint32_t ux, uy, uz, uw;
                lds128(sb + OWF(s) + SWZ(ro + c4 * 16), ux, uy, uz, uw);
                uint32_t h0, l0, h1, l1;
                cvt_pair(__uint_as_float(ux), __uint_as_float(uy), h0, l0);
                cvt_pair(__uint_as_float(uz), __uint_as_float(uw), h1, l1);
                sts64(sb + OWB(s) + SWZ(ro + c4 * 8), h0, h1);
                sts64(sb + OWB(s) + SWZ(ro + 64 + c4 * 8), l0, l1);
            }
            #pragma unroll
            for (int i = 0; i < 2; ++i) {
                const uint32_t ro = (uint32_t)((i * 32 + rb) * 128);
                uint32_t ux, uy, uz, uw;
                lds128(sb + OXF(s) + SWZ(ro + c4 * 16), ux, uy, uz, uw);
                uint32_t h0, l0, h1, l1;
                cvt_pair(__uint_as_float(ux), __uint_as_float(uy), h0, l0);
                cvt_pair(__uint_as_float(uz), __uint_as_float(uw), h1, l1);
                sts64(sb + OXB(s) + SWZ(ro + c4 * 8), h0, h1);
                sts64(sb + OXB(s) + SWZ(ro + 64 + c4 * 8), l0, l1);
            }
        };

        cpis(0);
        cpis(1);

        for (int t = 0; t < NTILES; ++t) {
            if (t + 1 < NTILES)
                asm volatile("cp.async.wait_group 1;" ::: "memory");
            else
                asm volatile("cp.async.wait_group 0;" ::: "memory");
            conv(t);
            if (t + 2 < NTILES) cpis(t + 2);
            __syncthreads();

            if (nmyt > 0) {
                const int s = t & 1;
                #pragma unroll
                for (int kk = 0; kk < 2; ++kk) {
                    uint32_t bh[4][2], bl[4][2];
                    const uint32_t kb0 = (uint32_t)(kk * 32 + (g4 & 1) * 16);
                    #pragma unroll
                    for (int nt = 0; nt < 4; ++nt) {
                        uint32_t rowb = (uint32_t)(n0w + nt * 8 + r8);
                        LDSM2(bh[nt][0], bh[nt][1], sb + OWB(s) + SWZ(rowb * 128 + kb0));
                        LDSM2(bl[nt][0], bl[nt][1], sb + OWB(s) + SWZ(rowb * 128 + kb0 + 64));
                    }
                    const uint32_t ka0 = (uint32_t)(kk * 32 + (g4 >> 1) * 16);
                    #pragma unroll
                    for (int j = 0; j < 2; ++j) {
                        if (j < nmyt) {              // uniform per warp-group
                            uint32_t rowa = (uint32_t)((mt0 + j) * 16 + r8 + (g4 & 1) * 8);
                            uint32_t ah[4], al[4];
                            LDSM4(ah[0], ah[1], ah[2], ah[3],
                                  sb + OXB(s) + SWZ(rowa * 128 + ka0));
                            LDSM4(al[0], al[1], al[2], al[3],
                                  sb + OXB(s) + SWZ(rowa * 128 + ka0 + 64));
                            #pragma unroll
                            for (int nt = 0; nt < 4; ++nt) {
                                MMA(c[j][nt], ah, bh[nt]);
                                MMA(c[j][nt], ah, bl[nt]);
                                MMA(c[j][nt], al, bh[nt]);
                            }
                        }
                    }
                }
            }
        }

        // epilogue (mappings validated in R15)
        const int gcol = (lane & 3) * 2;
        const int grow = lane >> 2;
        #pragma unroll
        for (int j = 0; j < 2; ++j) {
            if (j < nmyt) {
                #pragma unroll
                for (int h = 0; h < 2; ++h) {
                    int lr = (mt0 + j) * 16 + grow + h * 8;
                    int gr = mbase + lr;
                    if (gr < m) {
                        float* ob = out + (size_t)slist[gr] * OUTF + nq * NQ + n0w;
                        #pragma unroll
                        for (int nt = 0; nt < 4; ++nt) {
                            float2 v = make_float2(c[j][nt][2 * h], c[j][nt][2 * h + 1]);
                            *(float2*)(ob + nt * 8 + gcol) = v;
                        }
                    }
                }
            }
        }
        __syncthreads();
    }
}

extern "C" void kernel_launch(void* const* d_in, const int* in_sizes, int n_in,
                              void* d_out, int out_size)
{
    const float*    x   = nullptr;
    const unsigned* ids = nullptr;
    const float*    w   = nullptr;
    for (int i = 0; i < n_in; ++i) {
        if (in_sizes[i] == BB)                     ids = (const unsigned*)d_in[i];
        else if (in_sizes[i] == BB * INF)          x   = (const float*)d_in[i];
        else if (in_sizes[i] == NEXP * OUTF * INF) w   = (const float*)d_in[i];
    }
    cudaFuncSetAttribute(catlin_mma, cudaFuncAttributeMaxDynamicSharedMemorySize, DYN_BYTES);
    catlin_mma<<<NEXP * 4, T, DYN_BYTES>>>(x, ids, w, (float*)d_out);
}

// round 17
// speedup vs baseline: 1.1076x; 1.1076x over previous
#include <cuda_runtime.h>
#include <cstdint>

#define BB     2048
#define INF    512
#define OUTF   512
#define NEXP   64
#define T      256
#define NQ     128           // out cols per CTA
#define MCH    64            // m rows per chunk (4 x m16 max, split across warp halves)
#define KT     32            // fp32 k per tile -> 2 k16 mma steps
#define NTILES (INF / KT)    // 16

#define SWZ(o)  ((o) ^ (((o) >> 3) & 0x70))
#define OWB(s) ((uint32_t)(s) * 16384u)             // bf16 W: 128 rows x (64B hi | 64B lo)
#define OXB(s) (32768u + (uint32_t)(s) * 8192u)     // bf16 X: 64 rows x (hi|lo)
#define DYN_BYTES (49152 + 1024)

static __device__ __forceinline__ void sts64(uint32_t a, uint32_t v0, uint32_t v1) {
    asm volatile("st.shared.v2.b32 [%0], {%1,%2};" :: "r"(a), "r"(v0), "r"(v1));
}
// split fp32 pair -> bf16x2 hi (truncate) + bf16x2 lo (rn of residual); elem0 = first
static __device__ __forceinline__ void cvt_pair(float vx, float vy,
                                                uint32_t &hi2, uint32_t &lo2) {
    uint32_t a = __float_as_uint(vx), b = __float_as_uint(vy);
    hi2 = __byte_perm(a, b, 0x7632);
    float la = vx - __uint_as_float(a & 0xFFFF0000u);
    float lb = vy - __uint_as_float(b & 0xFFFF0000u);
    asm("cvt.rn.bf16x2.f32 %0, %1, %2;" : "=r"(lo2) : "f"(lb), "f"(la));
}
#define LDSM4(r0,r1,r2,r3,a) asm volatile( \
    "ldmatrix.sync.aligned.m8n8.x4.shared.b16 {%0,%1,%2,%3}, [%4];" \
    : "=r"(r0),"=r"(r1),"=r"(r2),"=r"(r3) : "r"(a))
#define LDSM2(r0,r1,a) asm volatile( \
    "ldmatrix.sync.aligned.m8n8.x2.shared.b16 {%0,%1}, [%2];" \
    : "=r"(r0),"=r"(r1) : "r"(a))
#define MMA(c,a,b) asm volatile( \
    "mma.sync.aligned.m16n8k16.row.col.f32.bf16.bf16.f32 " \
    "{%0,%1,%2,%3}, {%4,%5,%6,%7}, {%8,%9}, {%0,%1,%2,%3};" \
    : "+f"((c)[0]),"+f"((c)[1]),"+f"((c)[2]),"+f"((c)[3]) \
    : "r"((a)[0]),"r"((a)[1]),"r"((a)[2]),"r"((a)[3]),"r"((b)[0]),"r"((b)[1]))

extern __shared__ char dynsmem[];

__global__ __launch_bounds__(T, 2)
void catlin_mma(const float* __restrict__ x, const unsigned* __restrict__ idw,
                const float* __restrict__ weight, float* __restrict__ out)
{
    __shared__ uint16_t slist[BB];
    __shared__ int scount;
    __shared__ unsigned sor;

    const int expert = blockIdx.x >> 2;
    const int nq     = blockIdx.x & 3;
    const int tid    = threadIdx.x;
    const int wid    = tid >> 5, lane = tid & 31;

    if (tid == 0) { scount = 0; sor = 0; }
    __syncthreads();

    // int64 vs int32 id detection (first 2048 words are in-bounds either way)
    unsigned myor = 0;
    for (int i = tid; i < BB / 2; i += T) myor |= idw[2 * i + 1];
    if (myor) atomicOr(&sor, myor);
    __syncthreads();
    const bool is64 = (sor == 0);

    for (int i = tid; i < BB; i += T) {
        int id = is64 ? (int)idw[2 * i] : (int)idw[i];
        if (id == expert) { int p = atomicAdd(&scount, 1); slist[p] = (uint16_t)i; }
    }
    __syncthreads();
    const int m = scount;
    if (m == 0) return;

    uint32_t sb = (uint32_t)__cvta_generic_to_shared(dynsmem);
    sb = (sb + 1023u) & ~1023u;

    const float* wexp = weight + ((size_t)(expert * OUTF + nq * NQ)) * INF;
    const int wq  = wid & 3;         // n subtile: 32 cols
    const int wm  = wid >> 2;        // m group 0/1
    const int n0w = wq * 32;
    const int r8  = lane & 7;        // ldmatrix address role
    const int g4  = lane >> 3;
    const int c4  = tid & 7;         // float4 column within row (8 float4 per KT row)
    const int rb  = tid >> 3;        // row base 0..31

    float4 wst[4], ast[2];           // staged fp32 for next tile

    for (int mbase = 0; mbase < m; mbase += MCH) {
        const int rem = m - mbase;
        int nmt_tot = (rem + 15) >> 4; if (nmt_tot > 4) nmt_tot = 4;
        const int mh   = (nmt_tot + 1) >> 1;
        const int mt0  = wm ? mh : 0;
        const int nmyt = wm ? (nmt_tot - mh) : mh;

        // per-thread gathered X row pointers (identity map: thread loads rows i*32+rb)
        const float* xp[2];
        #pragma unroll
        for (int i = 0; i < 2; ++i) {
            int gr = mbase + i * 32 + rb; if (gr >= m) gr = m - 1;
            xp[i] = x + (size_t)slist[gr] * INF + c4 * 4;
        }

        float c[2][4][4];
        #pragma unroll
        for (int j = 0; j < 2; j++)
            #pragma unroll
            for (int b = 0; b < 4; b++)
                #pragma unroll
                for (int q = 0; q < 4; q++) c[j][b][q] = 0.f;

        auto ldg = [&](int t) {
            const int kb = t * KT;
            #pragma unroll
            for (int i = 0; i < 4; ++i)           // W: 128 rows x 8 float4
                wst[i] = *(const float4*)(wexp + (size_t)(i * 32 + rb) * INF + kb + c4 * 4);
            #pragma unroll
            for (int i = 0; i < 2; ++i)           // X: 64 rows x 8 float4
                ast[i] = *(const float4*)(xp[i] + kb);
        };
        auto sts = [&](int s) {
            #pragma unroll
            for (int i = 0; i < 4; ++i) {
                const uint32_t ro = (uint32_t)((i * 32 + rb) * 128);
                uint32_t h0, l0, h1, l1;
                cvt_pair(wst[i].x, wst[i].y, h0, l0);
                cvt_pair(wst[i].z, wst[i].w, h1, l1);
                sts64(sb + OWB(s) + SWZ(ro + (uint32_t)c4 * 8), h0, h1);
                sts64(sb + OWB(s) + SWZ(ro + 64 + (uint32_t)c4 * 8), l0, l1);
            }
            #pragma unroll
            for (int i = 0; i < 2; ++i) {
                const uint32_t ro = (uint32_t)((i * 32 + rb) * 128);
                uint32_t h0, l0, h1, l1;
                cvt_pair(ast[i].x, ast[i].y, h0, l0);
                cvt_pair(ast[i].z, ast[i].w, h1, l1);
                sts64(sb + OXB(s) + SWZ(ro + (uint32_t)c4 * 8), h0, h1);
                sts64(sb + OXB(s) + SWZ(ro + 64 + (uint32_t)c4 * 8), l0, l1);
            }
        };

        ldg(0);
        sts(0);
        __syncthreads();

        for (int t = 0; t < NTILES; ++t) {
            if (t + 1 < NTILES) ldg(t + 1);
            const int s = t & 1;

            #pragma unroll
            for (int kk = 0; kk < 2; ++kk) {      // two k16 steps per tile
                uint32_t bh[4][2], bl[4][2];
                const uint32_t kb0 = (uint32_t)(kk * 32 + (g4 & 1) * 16);
                #pragma unroll
                for (int nt = 0; nt < 4; ++nt) {
                    uint32_t rowb = (uint32_t)(n0w + nt * 8 + r8);
                    LDSM2(bh[nt][0], bh[nt][1], sb + OWB(s) + SWZ(rowb * 128 + kb0));
                    LDSM2(bl[nt][0], bl[nt][1], sb + OWB(s) + SWZ(rowb * 128 + kb0 + 64));
                }
                const uint32_t ka0 = (uint32_t)(kk * 32 + (g4 >> 1) * 16);
                #pragma unroll
                for (int j = 0; j < 2; ++j) {
                    if (j < nmyt) {               // uniform per warp-group
                        uint32_t rowa = (uint32_t)((mt0 + j) * 16 + r8 + (g4 & 1) * 8);
                        uint32_t ah[4], al[4];
                        LDSM4(ah[0], ah[1], ah[2], ah[3],
                              sb + OXB(s) + SWZ(rowa * 128 + ka0));
                        LDSM4(al[0], al[1], al[2], al[3],
                              sb + OXB(s) + SWZ(rowa * 128 + ka0 + 64));
                        #pragma unroll
                        for (int nt = 0; nt < 4; ++nt) {
                            MMA(c[j][nt], ah, bh[nt]);
                            MMA(c[j][nt], ah, bl[nt]);
                            MMA(c[j][nt], al, bh[nt]);
                        }
                    }
                }
            }

            if (t + 1 < NTILES) sts((t + 1) & 1);
            __syncthreads();
        }

        // epilogue (fragment->gmem mapping validated in R15)
        const int gcol = (lane & 3) * 2;
        const int grow = lane >> 2;
        #pragma unroll
        for (int j = 0; j < 2; ++j) {
            if (j < nmyt) {
                #pragma unroll
                for (int h = 0; h < 2; ++h) {
                    int lr = (mt0 + j) * 16 + grow + h * 8;
                    int gr = mbase + lr;
                    if (gr < m) {
                        float* ob = out + (size_t)slist[gr] * OUTF + nq * NQ + n0w;
                        #pragma unroll
                        for (int nt = 0; nt < 4; ++nt) {
                            float2 v = make_float2(c[j][nt][2 * h], c[j][nt][2 * h + 1]);
                            *(float2*)(ob + nt * 8 + gcol) = v;
                        }
                    }
                }
            }
        }
        __syncthreads();   // protect smem buffers before next chunk's prologue
    }
}

extern "C" void kernel_launch(void* const* d_in, const int* in_sizes, int n_in,
                              void* d_out, int out_size)
{
    const float*    x   = nullptr;
    const unsigned* ids = nullptr;
    const float*    w   = nullptr;
    for (int i = 0; i < n_in; ++i) {
        if (in_sizes[i] == BB)                     ids = (const unsigned*)d_in[i];
        else if (in_sizes[i] == BB * INF)          x   = (const float*)d_in[i];
        else if (in_sizes[i] == NEXP * OUTF * INF) w   = (const float*)d_in[i];
    }
    cudaFuncSetAttribute(catlin_mma, cudaFuncAttributeMaxDynamicSharedMemorySize, DYN_BYTES);
    catlin_mma<<<NEXP * 4, T, DYN_BYTES>>>(x, ids, w, (float*)d_out);
}